// round 14
// baseline (speedup 1.0000x reference)
#include <cuda_runtime.h>

// activation_moduleA: out[0:SIZE] = p = x[0:SIZE]
//                     out[SIZE:N] = weight * selu(p) + q,  q = x[SIZE:N]
// selu(v) = SCALE * (v > 0 ? v : ALPHA*(exp(v)-1))
//
// R14: persistent grid-stride. The R10 shape (8192 CTAs) runs ~18.5 waves
// over ~444 resident CTA slots (148 SM x 3 CTAs at 512 thr / 31 regs);
// the ragged tail + per-CTA churn is the last untried overhead. One CTA
// per resident slot (444), each looping over the problem. Per-iteration
// body identical to the proven best (MLP=3, plain LDG.128/STG.128).

#define SELU_SCALE 1.0507009873554804934193349852946f
#define SELU_ALPHA 1.6732632423543772848170429916717f

#define TPB 512
#define CTAS_PERSISTENT 444   // 148 SMs * 3 resident CTAs (512thr, ~31 regs)

__device__ __forceinline__ float selu_f(float v) {
    float neg = SELU_ALPHA * expm1f(v);
    return SELU_SCALE * (v > 0.0f ? v : neg);
}

__global__ void __launch_bounds__(TPB)
activation_kernel(const float4* __restrict__ x,
                  const float4* __restrict__ w,
                  float4* __restrict__ out,
                  int size4)   // SIZE/4 float4 elements per half
{
    const int stride = gridDim.x * TPB;
    for (int i = blockIdx.x * TPB + threadIdx.x; i < size4; i += stride) {
        float4 p  = x[i];
        float4 q  = x[i + size4];
        float4 wv = w[i];

        // first half: straight copy of p (store issues while SELU computes)
        out[i] = p;

        float4 r;
        r.x = fmaf(wv.x, selu_f(p.x), q.x);
        r.y = fmaf(wv.y, selu_f(p.y), q.y);
        r.z = fmaf(wv.z, selu_f(p.z), q.z);
        r.w = fmaf(wv.w, selu_f(p.w), q.w);
        out[i + size4] = r;
    }
}

extern "C" void kernel_launch(void* const* d_in, const int* in_sizes, int n_in,
                              void* d_out, int out_size) {
    const float* x = (const float*)d_in[0];
    const float* w = (const float*)d_in[1];
    float* out = (float*)d_out;

    const int N = in_sizes[0];          // 33554432
    const int SIZE = N / 2;             // 16777216
    const int size4 = SIZE / 4;         // 4194304 float4 per half

    activation_kernel<<<CTAS_PERSISTENT, TPB>>>(
        (const float4*)x, (const float4*)w, (float4*)out, size4);
}

// round 17
// speedup vs baseline: 1.0762x; 1.0762x over previous
#include <cuda_runtime.h>

// activation_moduleA: out[0:SIZE] = p = x[0:SIZE]
//                     out[SIZE:N] = weight * selu(p) + q,  q = x[SIZE:N]
// selu(v) = SCALE * (v > 0 ? v : ALPHA*(exp(v)-1))
//
// FINAL — session-best shape (R10: 52.96 us; re-bench 53.57 us, noise ±0.5).
// HBM-streaming-bound: ~320 MB logical / ~281 MB DRAM traffic per replay at
// the chip's effective mixed-R/W streaming ceiling (6.3-6.5 TB/s, ~80% of
// 8 TB/s spec). Explored and closed: deeper MLP (neutral), occupancy trades
// (neutral), cache-hint policies __ldcs/__stcs/__ldlu (neutral), PTX L2
// evict pinning (unsupported), persistent grid (regression: serialized
// loop kills inter-tile MLP that CTA churn provides for free).
// Shape: TPB=512, one float4-tile per thread, plain LDG.128/STG.128,
// guard-free exact-division path, regs 31, occ ~76%.

#define SELU_SCALE 1.0507009873554804934193349852946f
#define SELU_ALPHA 1.6732632423543772848170429916717f

#define TPB 512

__device__ __forceinline__ float selu_f(float v) {
    float neg = SELU_ALPHA * expm1f(v);
    return SELU_SCALE * (v > 0.0f ? v : neg);
}

template <bool GUARD>
__global__ void __launch_bounds__(TPB)
activation_kernel(const float4* __restrict__ x,
                  const float4* __restrict__ w,
                  float4* __restrict__ out,
                  int size4)   // SIZE/4 float4 elements per half
{
    int i = blockIdx.x * TPB + threadIdx.x;
    if (GUARD && i >= size4) return;

    float4 p  = x[i];
    float4 q  = x[i + size4];
    float4 wv = w[i];

    // first half: straight copy of p (store issues while SELU computes)
    out[i] = p;

    float4 r;
    r.x = fmaf(wv.x, selu_f(p.x), q.x);
    r.y = fmaf(wv.y, selu_f(p.y), q.y);
    r.z = fmaf(wv.z, selu_f(p.z), q.z);
    r.w = fmaf(wv.w, selu_f(p.w), q.w);
    out[i + size4] = r;
}

extern "C" void kernel_launch(void* const* d_in, const int* in_sizes, int n_in,
                              void* d_out, int out_size) {
    const float* x = (const float*)d_in[0];
    const float* w = (const float*)d_in[1];
    float* out = (float*)d_out;

    const int N = in_sizes[0];          // 33554432
    const int SIZE = N / 2;             // 16777216
    const int size4 = SIZE / 4;         // 4194304 float4 per half

    if (size4 % TPB == 0) {
        // exact division: no per-thread bounds guard (hit for this problem)
        activation_kernel<false><<<size4 / TPB, TPB>>>(
            (const float4*)x, (const float4*)w, (float4*)out, size4);
    } else {
        activation_kernel<true><<<(size4 + TPB - 1) / TPB, TPB>>>(
            (const float4*)x, (const float4*)w, (float4*)out, size4);
    }
}